// round 11
// baseline (speedup 1.0000x reference)
#include <cuda_runtime.h>

#define BB 8
#define CH 128
#define NN 2304
#define BM 128
#define BN 64
#define NT (NN / BN)

// Scratch (static device globals — allocation-free per harness rules)
__device__ float g_q[BB * CH * NN];
__device__ float g_k[BB * CH * NN];
__device__ float g_v[BB * CH * NN];
__device__ float g_pool[BB * CH];
__device__ float g_se[BB * CH];

union F2U { float2 f; unsigned long long u; };

// Packed dual fp32 FMA (Blackwell sm_100+): 2 FMA lanes per instruction.
__device__ __forceinline__ float2 ffma2(float2 a, float2 b, float2 c) {
    F2U A, B, C, D;
    A.f = a; B.f = b; C.f = c;
    asm("fma.rn.f32x2 %0, %1, %2, %3;" : "=l"(D.u) : "l"(A.u), "l"(B.u), "l"(C.u));
    return D.f;
}

// ---------------------------------------------------------------------------
// SE pooling: one block per (b,c) row. grid=1024 -> full-chip parallel.
// ---------------------------------------------------------------------------
__global__ void __launch_bounds__(128) se_pool_kernel(const float* __restrict__ x)
{
    const int row = blockIdx.x;                 // b*CH + c
    const int tid = threadIdx.x;
    const float4* xr = (const float4*)(x + (size_t)row * NN);

    float s = 0.f;
    for (int u = tid; u < NN / 4; u += 128) {
        float4 v = xr[u];
        s += (v.x + v.y) + (v.z + v.w);
    }
    #pragma unroll
    for (int off = 16; off > 0; off >>= 1)
        s += __shfl_down_sync(0xffffffffu, s, off);

    __shared__ float ws[4];
    if ((tid & 31) == 0) ws[tid >> 5] = s;
    __syncthreads();
    if (tid == 0)
        g_pool[row] = (ws[0] + ws[1] + ws[2] + ws[3]) * (1.f / (float)NN);
}

// ---------------------------------------------------------------------------
// SE FC: relu(w1 @ pool) -> sigmoid(w2 @ hid) -> g_se[b][c]. Tiny.
// ---------------------------------------------------------------------------
__global__ void __launch_bounds__(128) se_fc_kernel(
    const float* __restrict__ w1,   // (8,128)
    const float* __restrict__ w2)   // (128,8)
{
    __shared__ float pool[CH];
    __shared__ float hid[8];
    const int b = blockIdx.x;
    const int c = threadIdx.x;

    pool[c] = g_pool[b * CH + c];
    __syncthreads();

    if (c < 8) {
        float h = 0.f;
        #pragma unroll 4
        for (int k = 0; k < CH; ++k) h += w1[c * CH + k] * pool[k];
        hid[c] = fmaxf(h, 0.f);
    }
    __syncthreads();

    float s2 = 0.f;
    #pragma unroll
    for (int r = 0; r < 8; ++r) s2 += w2[c * 8 + r] * hid[r];
    g_se[b * CH + c] = 1.f / (1.f + __expf(-s2));
}

// ---------------------------------------------------------------------------
// QKV projections: out[b,o,n] = sum_c W[o,c] * x[b,c,n] + bias[o]
// grid (36, 8, 3). Tile 128(o) x 64(n), 256 threads, float4 register tiles.
// ---------------------------------------------------------------------------
__global__ void __launch_bounds__(256, 2) qkv_kernel(
    const float* __restrict__ x,
    const float* __restrict__ Wq, const float* __restrict__ bq,
    const float* __restrict__ Wk, const float* __restrict__ bk,
    const float* __restrict__ Wv, const float* __restrict__ bv)
{
    extern __shared__ float sm[];
    float* ws = sm;          // W transposed: ws[c][o], 128x128
    float* xs = sm + 16384;  // xs[c][j], 128x64

    const int z = blockIdx.z;
    const float* W    = (z == 0) ? Wq : (z == 1) ? Wk : Wv;
    const float* bias = (z == 0) ? bq : (z == 1) ? bk : bv;
    float* og         = (z == 0) ? g_q : (z == 1) ? g_k : g_v;

    const int b = blockIdx.y;
    const int n0 = blockIdx.x * 64;
    const int tid = threadIdx.x;

    {
        const int o = tid & 127, half = tid >> 7;
        const float* wr = W + o * CH + half * 64;
        #pragma unroll
        for (int u = 0; u < 16; ++u) {
            float4 w4 = *(const float4*)(wr + u * 4);
            const int cb = half * 64 + u * 4;
            ws[(cb + 0) * 128 + o] = w4.x;
            ws[(cb + 1) * 128 + o] = w4.y;
            ws[(cb + 2) * 128 + o] = w4.z;
            ws[(cb + 3) * 128 + o] = w4.w;
        }
    }
    #pragma unroll
    for (int it = 0; it < 8; ++it) {
        const int fi = it * 256 + tid;
        const int c = fi >> 4, f = fi & 15;
        *(float4*)(xs + c * 64 + f * 4) =
            *(const float4*)(x + (size_t)(b * CH + c) * NN + n0 + f * 4);
    }
    __syncthreads();

    const int to = tid & 15, tj = tid >> 4;
    // acc[jj][g][p]: o = to*4 + 64g + p*2 + {x:0, y:1}
    float2 acc[4][2][2];
    #pragma unroll
    for (int jj = 0; jj < 4; ++jj)
        #pragma unroll
        for (int g = 0; g < 2; ++g)
            #pragma unroll
            for (int p = 0; p < 2; ++p) acc[jj][g][p] = make_float2(0.f, 0.f);

    #pragma unroll 4
    for (int c = 0; c < CH; ++c) {
        const float* wr = ws + c * 128;
        float4 xv4 = *(const float4*)(xs + c * 64 + (tj << 2));
        float4 w0  = *(const float4*)(wr + to * 4);
        float4 w1  = *(const float4*)(wr + to * 4 + 64);
        const float xj[4] = {xv4.x, xv4.y, xv4.z, xv4.w};
        const float2 wp[2][2] = {{{w0.x, w0.y}, {w0.z, w0.w}},
                                 {{w1.x, w1.y}, {w1.z, w1.w}}};
        #pragma unroll
        for (int jj = 0; jj < 4; ++jj) {
            const float2 xb = make_float2(xj[jj], xj[jj]);
            #pragma unroll
            for (int g = 0; g < 2; ++g) {
                acc[jj][g][0] = ffma2(wp[g][0], xb, acc[jj][g][0]);
                acc[jj][g][1] = ffma2(wp[g][1], xb, acc[jj][g][1]);
            }
        }
    }

    #pragma unroll
    for (int g = 0; g < 2; ++g) {
        #pragma unroll
        for (int ce = 0; ce < 4; ++ce) {
            const int oo = to * 4 + 64 * g + ce;
            const int p = ce >> 1, e = ce & 1;
            const float bb = bias[oo];
            float* orow = og + (size_t)(b * CH + oo) * NN + n0 + (tj << 2);
            float4 r;
            r.x = (e ? acc[0][g][p].y : acc[0][g][p].x) + bb;
            r.y = (e ? acc[1][g][p].y : acc[1][g][p].x) + bb;
            r.z = (e ? acc[2][g][p].y : acc[2][g][p].x) + bb;
            r.w = (e ? acc[3][g][p].y : acc[3][g][p].x) + bb;
            *(float4*)orow = r;
        }
    }
}

// ---------------------------------------------------------------------------
// Attention + epilogue: out = gamma * softmax(QᵀK) applied to V + x*se
// grid (18, 8). Unnormalized streaming softmax (logits bounded ~|22|).
// Double-buffered K/V smem: K(t+1) via cp.async, V(t+1) via LDG->scatter STS.
// ---------------------------------------------------------------------------
#define K_OFF 16384
#define V_OFF 32768
#define P_OFF 49152
#define PROW  132
#define D_OFF (P_OFF + BN * PROW)     // 57600
#define SM_TOT (D_OFF + 128)          // 57728 floats = 230912 B

__global__ void __launch_bounds__(256, 1) attn_kernel(
    const float* __restrict__ x,
    const float* __restrict__ gamma,
    float* __restrict__ out)
{
    extern __shared__ float sm[];
    float* q_s   = sm;             // [c][i] 128x128
    float* k_sB  = sm + K_OFF;     // 2 x [c][j] 128x64
    float* v_sB  = sm + V_OFF;     // 2 x [j][c] 64x128, swizzle c ^ ((j>>1)&28)
    float* p_s   = sm + P_OFF;     // [j][i] 64x132 (padded rows)
    float* den_s = sm + D_OFF;     // [i] 128

    const int b  = blockIdx.y;
    const int n0 = blockIdx.x * BM;
    const int tid = threadIdx.x;
    const int ti  = tid & 15;   // S-phase: i = ti*4 + 64g + {0..3}
    const int tj  = tid >> 4;   // S-phase: j = tj*4 + jj
    const int tc  = tid & 15;   // PV: c = tc*4 + 64g' + {0..3}
    const int tip = tid >> 4;   // PV: i = tip*4 + 64h + {0..3}
    const int lth = tid >> 4;   // loader: c = it*16 + lth
    const int lf  = tid & 15;   // loader: j group

    const float* kgb = g_k + (size_t)(b * CH) * NN;
    const float* vgb = g_v + (size_t)(b * CH) * NN;

    // Load Q tile
    const float* qg = g_q + (size_t)(b * CH) * NN + n0;
    #pragma unroll
    for (int it = 0; it < 16; ++it) {
        const int fi = it * 256 + tid;
        const int c = fi >> 5, f = fi & 31;
        *(float4*)(q_s + c * 128 + f * 4) =
            *(const float4*)(qg + (size_t)c * NN + f * 4);
    }
    if (tid < 128) den_s[tid] = 0.f;

    // Prologue: tile 0 K/V (register path, once)
    {
        float4 kr[8], vr[8];
        #pragma unroll
        for (int it = 0; it < 8; ++it) {
            kr[it] = *(const float4*)(kgb + (size_t)(it * 16 + lth) * NN + lf * 4);
            vr[it] = *(const float4*)(vgb + (size_t)(it * 16 + lth) * NN + lf * 4);
        }
        const int j = lf * 4;
        const int sw = (lf * 2) & 28;
        #pragma unroll
        for (int it = 0; it < 8; ++it) {
            const int c = it * 16 + lth;
            *(float4*)(k_sB + c * 64 + j) = kr[it];
            v_sB[(j + 0) * 128 + (c ^ sw)] = vr[it].x;
            v_sB[(j + 1) * 128 + (c ^ sw)] = vr[it].y;
            v_sB[(j + 2) * 128 + (c ^ sw)] = vr[it].z;
            v_sB[(j + 3) * 128 + (c ^ sw)] = vr[it].w;
        }
    }

    float2 oacc[8][4];  // [c-sub a][i-quad pair q]
    #pragma unroll
    for (int a = 0; a < 8; ++a)
        #pragma unroll
        for (int q = 0; q < 4; ++q) oacc[a][q] = make_float2(0.f, 0.f);
    float4 dpart[2];
    dpart[0] = make_float4(0.f, 0.f, 0.f, 0.f);
    dpart[1] = make_float4(0.f, 0.f, 0.f, 0.f);

    __syncthreads();

    for (int t = 0; t < NT; ++t) {
        const int cur = t & 1;
        const float* kc = k_sB + cur * 8192;
        const float* vc = v_sB + cur * 8192;
        const bool pf = (t + 1 < NT);

        // Prefetch tile t+1: K via cp.async into alt buffer, V into regs.
        float4 vr[8];
        if (pf) {
            const int j0n = (t + 1) * BN;
            float* ka = k_sB + (cur ^ 1) * 8192;
            #pragma unroll
            for (int it = 0; it < 8; ++it) {
                unsigned sa = (unsigned)__cvta_generic_to_shared(
                    ka + (it * 16 + lth) * 64 + lf * 4);
                const float* gp = kgb + (size_t)(it * 16 + lth) * NN + j0n + lf * 4;
                asm volatile("cp.async.cg.shared.global [%0], [%1], 16;"
                             :: "r"(sa), "l"(gp));
            }
            asm volatile("cp.async.commit_group;");
            #pragma unroll
            for (int it = 0; it < 8; ++it)
                vr[it] = *(const float4*)(vgb + (size_t)(it * 16 + lth) * NN + j0n + lf * 4);
        }

        // --- S = QᵀK: per thread 8 i x 4 j ---
        float2 sacc[4][2][2];
        #pragma unroll
        for (int jj = 0; jj < 4; ++jj)
            #pragma unroll
            for (int g = 0; g < 2; ++g)
                #pragma unroll
                for (int p = 0; p < 2; ++p) sacc[jj][g][p] = make_float2(0.f, 0.f);

        #pragma unroll 4
        for (int c = 0; c < CH; ++c) {
            const float* qr = q_s + c * 128;
            float4 kv = *(const float4*)(kc + c * 64 + (tj << 2));
            float4 q0 = *(const float4*)(qr + ti * 4);
            float4 q1 = *(const float4*)(qr + ti * 4 + 64);
            const float kk[4] = {kv.x, kv.y, kv.z, kv.w};
            const float2 qp[2][2] = {{{q0.x, q0.y}, {q0.z, q0.w}},
                                     {{q1.x, q1.y}, {q1.z, q1.w}}};
            #pragma unroll
            for (int jj = 0; jj < 4; ++jj) {
                const float2 kb = make_float2(kk[jj], kk[jj]);
                #pragma unroll
                for (int g = 0; g < 2; ++g) {
                    sacc[jj][g][0] = ffma2(qp[g][0], kb, sacc[jj][g][0]);
                    sacc[jj][g][1] = ffma2(qp[g][1], kb, sacc[jj][g][1]);
                }
            }
        }

        // Store prefetched V (data long since arrived; overlapped with S math)
        if (pf) {
            float* va = v_sB + (cur ^ 1) * 8192;
            const int j = lf * 4;
            const int sw = (lf * 2) & 28;
            #pragma unroll
            for (int it = 0; it < 8; ++it) {
                const int c = it * 16 + lth;
                va[(j + 0) * 128 + (c ^ sw)] = vr[it].x;
                va[(j + 1) * 128 + (c ^ sw)] = vr[it].y;
                va[(j + 2) * 128 + (c ^ sw)] = vr[it].z;
                va[(j + 3) * 128 + (c ^ sw)] = vr[it].w;
            }
        }

        // exp -> P ([j][i], padded rows), accumulate denominator
        #pragma unroll
        for (int jj = 0; jj < 4; ++jj) {
            const int j = (tj << 2) + jj;
            float* pd = p_s + j * PROW + ti * 4;
            #pragma unroll
            for (int g = 0; g < 2; ++g) {
                float4 pw;
                pw.x = __expf(sacc[jj][g][0].x);
                pw.y = __expf(sacc[jj][g][0].y);
                pw.z = __expf(sacc[jj][g][1].x);
                pw.w = __expf(sacc[jj][g][1].y);
                dpart[g].x += pw.x; dpart[g].y += pw.y;
                dpart[g].z += pw.z; dpart[g].w += pw.w;
                *(float4*)(pd + 64 * g) = pw;
            }
        }
        __syncthreads();

        // --- O += V * Pᵀ: per thread 8 c x 8 i ---
        #pragma unroll 2
        for (int j = 0; j < BN; ++j) {
            const float* pr = p_s + j * PROW;
            const float* vrow = vc + j * 128;
            const int sw = (j >> 1) & 28;
            float4 p0 = *(const float4*)(pr + tip * 4);
            float4 p1 = *(const float4*)(pr + tip * 4 + 64);
            float4 va4 = *(const float4*)(vrow + ((tc * 4) ^ sw));
            float4 vb4 = *(const float4*)(vrow + (((tc * 4) + 64) ^ sw));
            const float2 pv[4] = {{p0.x, p0.y}, {p0.z, p0.w},
                                  {p1.x, p1.y}, {p1.z, p1.w}};
            const float vsc[8] = {va4.x, va4.y, va4.z, va4.w,
                                  vb4.x, vb4.y, vb4.z, vb4.w};
            #pragma unroll
            for (int a = 0; a < 8; ++a) {
                const float2 vb2 = make_float2(vsc[a], vsc[a]);
                #pragma unroll
                for (int q = 0; q < 4; ++q)
                    oacc[a][q] = ffma2(vb2, pv[q], oacc[a][q]);
            }
        }

        if (pf) asm volatile("cp.async.wait_group 0;");
        __syncthreads();
    }

    // Reduce denominator across tj groups
    #pragma unroll
    for (int g = 0; g < 2; ++g) {
        const int base = ti * 4 + 64 * g;
        atomicAdd(&den_s[base + 0], dpart[g].x);
        atomicAdd(&den_s[base + 1], dpart[g].y);
        atomicAdd(&den_s[base + 2], dpart[g].z);
        atomicAdd(&den_s[base + 3], dpart[g].w);
    }
    __syncthreads();

    // Epilogue: out = gamma * O/den + x * se
    const float gm = gamma[0];
    float rden[8];
    {
        float4 rd0 = *(const float4*)(den_s + tip * 4);
        float4 rd1 = *(const float4*)(den_s + tip * 4 + 64);
        rden[0] = 1.f / rd0.x; rden[1] = 1.f / rd0.y;
        rden[2] = 1.f / rd0.z; rden[3] = 1.f / rd0.w;
        rden[4] = 1.f / rd1.x; rden[5] = 1.f / rd1.y;
        rden[6] = 1.f / rd1.z; rden[7] = 1.f / rd1.w;
    }
    #pragma unroll
    for (int a = 0; a < 8; ++a) {
        const int c = tc * 4 + (a & 3) + 64 * (a >> 2);
        const float sev = g_se[b * CH + c];
        const float* xr = x + (size_t)(b * CH + c) * NN + n0;
        float* orow = out + (size_t)(b * CH + c) * NN + n0;
        #pragma unroll
        for (int h = 0; h < 2; ++h) {
            const int i = tip * 4 + 64 * h;
            float4 x4 = *(const float4*)(xr + i);
            float4 r;
            r.x = gm * oacc[a][h * 2 + 0].x * rden[h * 4 + 0] + x4.x * sev;
            r.y = gm * oacc[a][h * 2 + 0].y * rden[h * 4 + 1] + x4.y * sev;
            r.z = gm * oacc[a][h * 2 + 1].x * rden[h * 4 + 2] + x4.z * sev;
            r.w = gm * oacc[a][h * 2 + 1].y * rden[h * 4 + 3] + x4.w * sev;
            *(float4*)(orow + i) = r;
        }
    }
}

// ---------------------------------------------------------------------------
extern "C" void kernel_launch(void* const* d_in, const int* in_sizes, int n_in,
                              void* d_out, int out_size) {
    const float* x     = (const float*)d_in[0];
    const float* Wq    = (const float*)d_in[1];
    const float* bq    = (const float*)d_in[2];
    const float* Wk    = (const float*)d_in[3];
    const float* bk    = (const float*)d_in[4];
    const float* Wv    = (const float*)d_in[5];
    const float* bv    = (const float*)d_in[6];
    const float* w1    = (const float*)d_in[7];
    const float* w2    = (const float*)d_in[8];
    const float* gamma = (const float*)d_in[9];
    float* out = (float*)d_out;

    const int qkv_smem  = 24576 * 4;    // 96 KB
    const int attn_smem = SM_TOT * 4;   // 230912 B (< 227 KB opt-in cap)
    cudaFuncSetAttribute(qkv_kernel,  cudaFuncAttributeMaxDynamicSharedMemorySize, qkv_smem);
    cudaFuncSetAttribute(attn_kernel, cudaFuncAttributeMaxDynamicSharedMemorySize, attn_smem);

    se_pool_kernel<<<BB * CH, 128>>>(x);
    qkv_kernel<<<dim3(NN / 64, BB, 3), 256, qkv_smem>>>(x, Wq, bq, Wk, bk, Wv, bv);
    se_fc_kernel<<<BB, 128>>>(w1, w2);
    attn_kernel<<<dim3(NN / BM, BB), 256, attn_smem>>>(x, gamma, out);
}

// round 12
// speedup vs baseline: 1.5284x; 1.5284x over previous
#include <cuda_runtime.h>

#define BB 8
#define CH 128
#define NN 2304
#define BM 128
#define BN 64
#define NT (NN / BN)

// Scratch (static device globals — allocation-free per harness rules)
__device__ float g_q[BB * CH * NN];
__device__ float g_k[BB * CH * NN];
__device__ float g_v[BB * CH * NN];
__device__ float g_pool[BB * CH];
__device__ float g_se[BB * CH];

union F2U { float2 f; unsigned long long u; };

// Packed dual fp32 FMA (Blackwell sm_100+): 2 FMA lanes per instruction.
__device__ __forceinline__ float2 ffma2(float2 a, float2 b, float2 c) {
    F2U A, B, C, D;
    A.f = a; B.f = b; C.f = c;
    asm("fma.rn.f32x2 %0, %1, %2, %3;" : "=l"(D.u) : "l"(A.u), "l"(B.u), "l"(C.u));
    return D.f;
}

// ---------------------------------------------------------------------------
// SE pooling: one block per (b,c) row. grid=1024 -> full-chip parallel.
// ---------------------------------------------------------------------------
__global__ void __launch_bounds__(128) se_pool_kernel(const float* __restrict__ x)
{
    const int row = blockIdx.x;                 // b*CH + c
    const int tid = threadIdx.x;
    const float4* xr = (const float4*)(x + (size_t)row * NN);

    float s = 0.f;
    for (int u = tid; u < NN / 4; u += 128) {
        float4 v = xr[u];
        s += (v.x + v.y) + (v.z + v.w);
    }
    #pragma unroll
    for (int off = 16; off > 0; off >>= 1)
        s += __shfl_down_sync(0xffffffffu, s, off);

    __shared__ float ws[4];
    if ((tid & 31) == 0) ws[tid >> 5] = s;
    __syncthreads();
    if (tid == 0)
        g_pool[row] = (ws[0] + ws[1] + ws[2] + ws[3]) * (1.f / (float)NN);
}

// ---------------------------------------------------------------------------
// SE FC: relu(w1 @ pool) -> sigmoid(w2 @ hid) -> g_se[b][c]. Tiny.
// ---------------------------------------------------------------------------
__global__ void __launch_bounds__(128) se_fc_kernel(
    const float* __restrict__ w1,   // (8,128)
    const float* __restrict__ w2)   // (128,8)
{
    __shared__ float pool[CH];
    __shared__ float hid[8];
    const int b = blockIdx.x;
    const int c = threadIdx.x;

    pool[c] = g_pool[b * CH + c];
    __syncthreads();

    if (c < 8) {
        float h = 0.f;
        #pragma unroll 4
        for (int k = 0; k < CH; ++k) h += w1[c * CH + k] * pool[k];
        hid[c] = fmaxf(h, 0.f);
    }
    __syncthreads();

    float s2 = 0.f;
    #pragma unroll
    for (int r = 0; r < 8; ++r) s2 += w2[c * 8 + r] * hid[r];
    g_se[b * CH + c] = 1.f / (1.f + __expf(-s2));
}

// ---------------------------------------------------------------------------
// QKV projections: out[b,o,n] = sum_c W[o,c] * x[b,c,n] + bias[o]
// grid (36, 8, 3). Tile 128(o) x 64(n), 256 threads. float2 operand feeds
// (FFMA2 needs float2-loaded operands; float4 extraction costs MOVs on fma pipe).
// ---------------------------------------------------------------------------
__global__ void __launch_bounds__(256, 2) qkv_kernel(
    const float* __restrict__ x,
    const float* __restrict__ Wq, const float* __restrict__ bq,
    const float* __restrict__ Wk, const float* __restrict__ bk,
    const float* __restrict__ Wv, const float* __restrict__ bv)
{
    extern __shared__ float sm[];
    float* ws = sm;          // W transposed: ws[c][o], 128x128
    float* xs = sm + 16384;  // xs[c][j], 128x64

    const int z = blockIdx.z;
    const float* W    = (z == 0) ? Wq : (z == 1) ? Wk : Wv;
    const float* bias = (z == 0) ? bq : (z == 1) ? bk : bv;
    float* og         = (z == 0) ? g_q : (z == 1) ? g_k : g_v;

    const int b = blockIdx.y;
    const int n0 = blockIdx.x * 64;
    const int tid = threadIdx.x;

    {
        const int o = tid & 127, half = tid >> 7;
        const float* wr = W + o * CH + half * 64;
        #pragma unroll
        for (int u = 0; u < 16; ++u) {
            float4 w4 = *(const float4*)(wr + u * 4);
            const int cb = half * 64 + u * 4;
            ws[(cb + 0) * 128 + o] = w4.x;
            ws[(cb + 1) * 128 + o] = w4.y;
            ws[(cb + 2) * 128 + o] = w4.z;
            ws[(cb + 3) * 128 + o] = w4.w;
        }
    }
    #pragma unroll
    for (int it = 0; it < 8; ++it) {
        const int fi = it * 256 + tid;
        const int c = fi >> 4, f = fi & 15;
        *(float4*)(xs + c * 64 + f * 4) =
            *(const float4*)(x + (size_t)(b * CH + c) * NN + n0 + f * 4);
    }
    __syncthreads();

    const int to = tid & 15, tj = tid >> 4;
    float2 acc[4][4];  // [jj][g], o = to*2 + 32g + {0,1}
    #pragma unroll
    for (int jj = 0; jj < 4; ++jj)
        #pragma unroll
        for (int g = 0; g < 4; ++g) acc[jj][g] = make_float2(0.f, 0.f);

    #pragma unroll 2
    for (int c = 0; c < CH; ++c) {
        const float* wr = ws + c * 128;
        float4 xv4 = *(const float4*)(xs + c * 64 + (tj << 2));
        float2 wv[4];
        #pragma unroll
        for (int g = 0; g < 4; ++g)
            wv[g] = *(const float2*)(wr + to * 2 + 32 * g);
        const float xj[4] = {xv4.x, xv4.y, xv4.z, xv4.w};
        #pragma unroll
        for (int jj = 0; jj < 4; ++jj) {
            const float2 xb = make_float2(xj[jj], xj[jj]);
            #pragma unroll
            for (int g = 0; g < 4; ++g)
                acc[jj][g] = ffma2(wv[g], xb, acc[jj][g]);
        }
    }

    #pragma unroll
    for (int g = 0; g < 4; ++g) {
        #pragma unroll
        for (int e = 0; e < 2; ++e) {
            const int oo = to * 2 + 32 * g + e;
            const float bb = bias[oo];
            float* orow = og + (size_t)(b * CH + oo) * NN + n0 + (tj << 2);
            float4 r;
            r.x = (e ? acc[0][g].y : acc[0][g].x) + bb;
            r.y = (e ? acc[1][g].y : acc[1][g].x) + bb;
            r.z = (e ? acc[2][g].y : acc[2][g].x) + bb;
            r.w = (e ? acc[3][g].y : acc[3][g].x) + bb;
            *(float4*)orow = r;
        }
    }
}

// ---------------------------------------------------------------------------
// Attention + epilogue: out = gamma * softmax(QᵀK) applied to V + x*se
// grid (18, 8). Unnormalized streaming softmax (logits bounded ~|22|).
// Round-9 float2 inner loops (FFMA2-friendly) + double-buffered K/V smem:
// K(t+1) via cp.async, V(t+1) via LDG->scatter STS after the S c-loop.
// ---------------------------------------------------------------------------
#define K_OFF 16384
#define V_OFF 32768
#define P_OFF 49152
#define D_OFF (P_OFF + BN * 128)      // 57344
#define SM_TOT (D_OFF + 128)          // 57472 floats = 229888 B

__global__ void __launch_bounds__(256, 1) attn_kernel(
    const float* __restrict__ x,
    const float* __restrict__ gamma,
    float* __restrict__ out)
{
    extern __shared__ float sm[];
    float* q_s   = sm;             // [c][i] 128x128
    float* k_sB  = sm + K_OFF;     // 2 x [c][j] 128x64
    float* v_sB  = sm + V_OFF;     // 2 x [j][c] 64x128, swizzle c ^ ((j>>1)&30)
    float* p_s   = sm + P_OFF;     // [j][i] 64x128
    float* den_s = sm + D_OFF;     // [i] 128

    const int b  = blockIdx.y;
    const int n0 = blockIdx.x * BM;
    const int tid = threadIdx.x;
    const int ti  = tid & 15;   // S-phase: i = ti*2 + 32g + {0,1}
    const int tj  = tid >> 4;   // S-phase: j = tj*4 + jj
    const int tc  = tid & 15;   // PV: c = tc*2 + 32g + {0,1}
    const int tip = tid >> 4;   // PV: i = tip*2 + 32h + {0,1}
    const int lth = tid >> 4;   // loader: c = it*16 + lth
    const int lf  = tid & 15;   // loader: j group

    const float* kgb = g_k + (size_t)(b * CH) * NN;
    const float* vgb = g_v + (size_t)(b * CH) * NN;

    // Load Q tile
    const float* qg = g_q + (size_t)(b * CH) * NN + n0;
    #pragma unroll
    for (int it = 0; it < 16; ++it) {
        const int fi = it * 256 + tid;
        const int c = fi >> 5, f = fi & 31;
        *(float4*)(q_s + c * 128 + f * 4) =
            *(const float4*)(qg + (size_t)c * NN + f * 4);
    }
    if (tid < 128) den_s[tid] = 0.f;

    // Prologue: tile 0 K/V -> regs -> smem buffer 0
    {
        float4 kr[8], vr[8];
        #pragma unroll
        for (int it = 0; it < 8; ++it) {
            kr[it] = *(const float4*)(kgb + (size_t)(it * 16 + lth) * NN + lf * 4);
            vr[it] = *(const float4*)(vgb + (size_t)(it * 16 + lth) * NN + lf * 4);
        }
        const int j = lf * 4;
        #pragma unroll
        for (int it = 0; it < 8; ++it) {
            const int c = it * 16 + lth;
            *(float4*)(k_sB + c * 64 + j) = kr[it];
            v_sB[(j + 0) * 128 + (c ^ (((j + 0) >> 1) & 30))] = vr[it].x;
            v_sB[(j + 1) * 128 + (c ^ (((j + 1) >> 1) & 30))] = vr[it].y;
            v_sB[(j + 2) * 128 + (c ^ (((j + 2) >> 1) & 30))] = vr[it].z;
            v_sB[(j + 3) * 128 + (c ^ (((j + 3) >> 1) & 30))] = vr[it].w;
        }
    }

    float2 oacc[8][4];  // [c-sub (g*2+e)][i-pair h] numerator accumulators
    #pragma unroll
    for (int a = 0; a < 8; ++a)
        #pragma unroll
        for (int h = 0; h < 4; ++h) oacc[a][h] = make_float2(0.f, 0.f);
    float2 dpart[4];
    #pragma unroll
    for (int g = 0; g < 4; ++g) dpart[g] = make_float2(0.f, 0.f);

    __syncthreads();

    for (int t = 0; t < NT; ++t) {
        const int cur = t & 1;
        const float* kc = k_sB + cur * 8192;
        const float* vc = v_sB + cur * 8192;
        const bool pf = (t + 1 < NT);

        // Prefetch tile t+1: K via cp.async into alt buffer, V into regs.
        float4 vr[8];
        if (pf) {
            const int j0n = (t + 1) * BN;
            float* ka = k_sB + (cur ^ 1) * 8192;
            #pragma unroll
            for (int it = 0; it < 8; ++it) {
                unsigned sa = (unsigned)__cvta_generic_to_shared(
                    ka + (it * 16 + lth) * 64 + lf * 4);
                const float* gp = kgb + (size_t)(it * 16 + lth) * NN + j0n + lf * 4;
                asm volatile("cp.async.cg.shared.global [%0], [%1], 16;"
                             :: "r"(sa), "l"(gp));
            }
            asm volatile("cp.async.commit_group;");
            #pragma unroll
            for (int it = 0; it < 8; ++it)
                vr[it] = *(const float4*)(vgb + (size_t)(it * 16 + lth) * NN + j0n + lf * 4);
        }

        // --- S = QᵀK: per thread 8 i x 4 j (float2 operand feeds) ---
        float2 sacc[4][4];
        #pragma unroll
        for (int jj = 0; jj < 4; ++jj)
            #pragma unroll
            for (int g = 0; g < 4; ++g) sacc[jj][g] = make_float2(0.f, 0.f);

        #pragma unroll 2
        for (int c = 0; c < CH; ++c) {
            const float* qr = q_s + c * 128;
            float4 kv = *(const float4*)(kc + c * 64 + (tj << 2));
            float2 qv[4];
            #pragma unroll
            for (int g = 0; g < 4; ++g)
                qv[g] = *(const float2*)(qr + ti * 2 + 32 * g);
            const float kk[4] = {kv.x, kv.y, kv.z, kv.w};
            #pragma unroll
            for (int jj = 0; jj < 4; ++jj) {
                const float2 kb = make_float2(kk[jj], kk[jj]);
                #pragma unroll
                for (int g = 0; g < 4; ++g)
                    sacc[jj][g] = ffma2(qv[g], kb, sacc[jj][g]);
            }
        }

        // Store prefetched V into alt buffer (data arrived during S math)
        if (pf) {
            float* va = v_sB + (cur ^ 1) * 8192;
            const int j = lf * 4;
            #pragma unroll
            for (int it = 0; it < 8; ++it) {
                const int c = it * 16 + lth;
                va[(j + 0) * 128 + (c ^ (((j + 0) >> 1) & 30))] = vr[it].x;
                va[(j + 1) * 128 + (c ^ (((j + 1) >> 1) & 30))] = vr[it].y;
                va[(j + 2) * 128 + (c ^ (((j + 2) >> 1) & 30))] = vr[it].z;
                va[(j + 3) * 128 + (c ^ (((j + 3) >> 1) & 30))] = vr[it].w;
            }
        }

        // exp -> P ([j][i]), accumulate denominator
        #pragma unroll
        for (int jj = 0; jj < 4; ++jj) {
            const int j = (tj << 2) + jj;
            #pragma unroll
            for (int g = 0; g < 4; ++g) {
                float2 p;
                p.x = __expf(sacc[jj][g].x);
                p.y = __expf(sacc[jj][g].y);
                dpart[g].x += p.x;
                dpart[g].y += p.y;
                *(float2*)(p_s + j * 128 + ti * 2 + 32 * g) = p;
            }
        }
        __syncthreads();

        // --- O += V * Pᵀ: per thread 8 c x 8 i ---
        #pragma unroll 2
        for (int j = 0; j < BN; ++j) {
            const float* pr = p_s + j * 128;
            const float* vrow = vc + j * 128;
            const int sw = (j >> 1) & 30;
            float2 pv[4];
            #pragma unroll
            for (int h = 0; h < 4; ++h)
                pv[h] = *(const float2*)(pr + tip * 2 + 32 * h);
            #pragma unroll
            for (int g = 0; g < 4; ++g) {
                float2 vv = *(const float2*)(vrow + ((tc * 2 + 32 * g) ^ sw));
                const float2 v0 = make_float2(vv.x, vv.x);
                const float2 v1 = make_float2(vv.y, vv.y);
                #pragma unroll
                for (int h = 0; h < 4; ++h) {
                    oacc[g * 2 + 0][h] = ffma2(v0, pv[h], oacc[g * 2 + 0][h]);
                    oacc[g * 2 + 1][h] = ffma2(v1, pv[h], oacc[g * 2 + 1][h]);
                }
            }
        }

        if (pf) asm volatile("cp.async.wait_group 0;");
        __syncthreads();
    }

    // Reduce denominator across tj groups
    #pragma unroll
    for (int g = 0; g < 4; ++g) {
        atomicAdd(&den_s[ti * 2 + 32 * g], dpart[g].x);
        atomicAdd(&den_s[ti * 2 + 32 * g + 1], dpart[g].y);
    }
    __syncthreads();

    // Epilogue: out = gamma * O/den + x * se
    const float gm = gamma[0];
    float rden[8];
    #pragma unroll
    for (int h = 0; h < 4; ++h) {
        rden[2 * h]     = 1.f / den_s[tip * 2 + 32 * h];
        rden[2 * h + 1] = 1.f / den_s[tip * 2 + 32 * h + 1];
    }
    #pragma unroll
    for (int g = 0; g < 4; ++g) {
        #pragma unroll
        for (int e = 0; e < 2; ++e) {
            const int c = tc * 2 + 32 * g + e;
            const float sev = g_se[b * CH + c];
            const float* xr = x + (size_t)(b * CH + c) * NN + n0;
            float* orow = out + (size_t)(b * CH + c) * NN + n0;
            #pragma unroll
            for (int h = 0; h < 4; ++h) {
                const int i = tip * 2 + 32 * h;
                float2 xv = *(const float2*)(xr + i);
                float2 a = oacc[g * 2 + e][h];
                float2 r;
                r.x = gm * a.x * rden[2 * h]     + xv.x * sev;
                r.y = gm * a.y * rden[2 * h + 1] + xv.y * sev;
                *(float2*)(orow + i) = r;
            }
        }
    }
}

// ---------------------------------------------------------------------------
extern "C" void kernel_launch(void* const* d_in, const int* in_sizes, int n_in,
                              void* d_out, int out_size) {
    const float* x     = (const float*)d_in[0];
    const float* Wq    = (const float*)d_in[1];
    const float* bq    = (const float*)d_in[2];
    const float* Wk    = (const float*)d_in[3];
    const float* bk    = (const float*)d_in[4];
    const float* Wv    = (const float*)d_in[5];
    const float* bv    = (const float*)d_in[6];
    const float* w1    = (const float*)d_in[7];
    const float* w2    = (const float*)d_in[8];
    const float* gamma = (const float*)d_in[9];
    float* out = (float*)d_out;

    const int qkv_smem  = 24576 * 4;    // 96 KB
    const int attn_smem = SM_TOT * 4;   // 229888 B (< 227 KB opt-in cap)
    cudaFuncSetAttribute(qkv_kernel,  cudaFuncAttributeMaxDynamicSharedMemorySize, qkv_smem);
    cudaFuncSetAttribute(attn_kernel, cudaFuncAttributeMaxDynamicSharedMemorySize, attn_smem);

    se_pool_kernel<<<BB * CH, 128>>>(x);
    qkv_kernel<<<dim3(NN / 64, BB, 3), 256, qkv_smem>>>(x, Wq, bq, Wk, bk, Wv, bv);
    se_fc_kernel<<<BB, 128>>>(w1, w2);
    attn_kernel<<<dim3(NN / BM, BB), 256, attn_smem>>>(x, gamma, out);
}